// round 14
// baseline (speedup 1.0000x reference)
#include <cuda_runtime.h>
#include <math.h>

#define BB 2
#define DD 64
#define HH 96
#define WW 96
#define VOL (DD*HH*WW)          // 589824
#define NVOX (BB*VOL)           // 1179648
#define HWSZ (HH*WW)            // 9216
#define NPLANE (BB*DD)          // 128
#define HT 24                   // passBC h-tile (4 per plane)
#define WT3 32                  // pass3 w-tile
#define CLAMP 25.0f

#define NBLKBC (NPLANE*4)       // 512 passBC blocks
#define NBLK3 (BB*HH*(WW/WT3))  // 576 pass3 blocks

// Scratch (device globals: allocation-free per harness rules)
__device__ float g_x[NVOX];               // packed bp-bn after W+H transform (clamped 25)
__device__ volatile float g_pn[NBLK3];
__device__ volatile float g_pd[NBLK3];
__device__ unsigned g_count;              // zero-init; last block resets -> deterministic

// Distance (voxels) from w (0..95) to nearest set bit of the 96-bit row mask
// {lo: bits 0-63, hi: bits 64-95}. Returns huge if none. (Validated r2-r6.)
__device__ __forceinline__ int nearest_bit(unsigned long long lo, unsigned hi, int w) {
    const int INF = 1 << 30;
    int up = INF, down = INF;
    if (w < 64) {
        unsigned long long a = lo >> w;
        if (a) up = __ffsll((long long)a) - 1;
        else if (hi) up = (64 - w) + (__ffs((int)hi) - 1);
        unsigned long long b = lo << (63 - w);
        if (b) down = __clzll((long long)b);
    } else {
        int w2 = w - 64;
        unsigned a = hi >> w2;
        if (a) up = __ffs((int)a) - 1;
        unsigned b = hi << (31 - w2);
        if (b) down = __clz((int)b);
        else if (lo) down = (w2 + 1) + __clzll((long long)lo);
    }
    return (up < down) ? up : down;
}

// Fused: ballot mask build + pass1 (clamped W bit-scan) + pass2 (k=1..4
// branch-free H stencil). Block = (plane, full-W h-tile of 24). 256 threads.
// tgt is read with only 1.33x redundancy (h-halo), no w redundancy.
__global__ __launch_bounds__(256) void k_passBC(const float* __restrict__ tgt) {
    __shared__ unsigned sm[32][3];      // rows h0-4..h0+27, full 96-bit masks
    __shared__ float s1p[32][WW];       // pass1 fpos (tid-contiguous access)
    __shared__ float s1n[32][WW];

    int ht = blockIdx.x & 3;
    int bd = blockIdx.x >> 2;
    int base = bd * HWSZ;
    int h0 = ht * HT;
    int tid = threadIdx.x;
    int lane = tid & 31;
    int warp = tid >> 5;                // 0..7

    // Ballot masks: 32 rows x 3 segs = 96 warp-tasks, 12 per warp.
    #pragma unroll
    for (int task = warp; task < 96; task += 8) {
        int r = task / 3;
        int s = task - r * 3;
        int hr = h0 - 4 + r;
        unsigned m = 0;
        if (hr >= 0 && hr < HH) {
            float v = tgt[base + hr * WW + s * 32 + lane];
            m = __ballot_sync(0xFFFFFFFFu, v > 0.5f);
        }
        if (lane == 0) sm[r][s] = m;
    }
    __syncthreads();

    // pass1: clamped W-distance via full-row bit scan; 12 voxels per thread.
    #pragma unroll 1
    for (int v = tid; v < 32 * WW; v += 256) {
        int r = v / WW;
        int w = v - r * WW;
        int hr = h0 - 4 + r;
        float vp, vn;
        if (hr < 0 || hr >= HH) {
            vp = CLAMP; vn = CLAMP;
        } else {
            unsigned long long lo = (unsigned long long)sm[r][0]
                                  | ((unsigned long long)sm[r][1] << 32);
            unsigned hi = sm[r][2];
            int dn = nearest_bit(lo, hi, w);        // nearest 1
            int dp = nearest_bit(~lo, ~hi, w);      // nearest 0
            vp = (dp >= 5) ? CLAMP : (float)(dp * dp);
            vn = (dn >= 5) ? CLAMP : (float)(dn * dn);
        }
        s1p[0][v] = vp;     // linear layout: row r, col w at offset r*96+w
        s1n[0][v] = vn;
    }
    __syncthreads();

    // pass2 along H: fixed k=1..4 stencil (exact under clamp), 9 voxels/thread.
    #pragma unroll 1
    for (int v = tid; v < HT * WW; v += 256) {
        int i = v / WW;
        int c = v - i * WW;
        int rr = (i + 4) * WW + c;      // center row in smem linear space
        float bp = s1p[0][rr];
        float bn = s1n[0][rr];
        #pragma unroll
        for (int k = 1; k <= 4; ++k) {
            float k2 = (float)(k * k);
            bp = fminf(bp, s1p[0][rr - k * WW] + k2);
            bp = fminf(bp, s1p[0][rr + k * WW] + k2);
            bn = fminf(bn, s1n[0][rr - k * WW] + k2);
            bn = fminf(bn, s1n[0][rr + k * WW] + k2);
        }
        // Exactly one of bp,bn is 0 -> pack as signed value. Coalesced write.
        g_x[base + (h0 + i) * WW + c] = bp - bn;
    }
}

// Pass3: k=1..4 D-stencil with 4-consecutive-i register reuse (round-10 shape),
// 512 threads / WT3=32, fused loss epilogue + grid-final reduction.
__global__ __launch_bounds__(512) void k_pass3(const float* __restrict__ pred,
                                               float* __restrict__ out) {
    __shared__ float sfp[DD + 8][33];   // stride 33: lane=w conflict-free
    __shared__ float sfn[DD + 8][33];
    __shared__ float rnm[16], rdm[16];
    __shared__ int s_last;

    int wt = blockIdx.x % (WW / WT3);       // 0..2
    int bh = blockIdx.x / (WW / WT3);
    int b = bh / HH;
    int h = bh % HH;
    int base = b * VOL + h * WW + wt * WT3;
    int tid = threadIdx.x;
    int w = tid & 31;
    int c0 = tid >> 5;                      // 0..15
    int i0 = c0 * 4;                        // 4 consecutive i per thread

    // Issue pred LDGs first (latency hidden behind smem fill + stencil).
    float pv[4];
    #pragma unroll
    for (int j = 0; j < 4; ++j) pv[j] = pred[base + (i0 + j) * HWSZ + w];

    // Pad rows [0..3] and [DD+4..DD+7].
    if (tid < 256) {
        int r = tid >> 5;                   // 0..7
        int ww_ = tid & 31;
        int row = (r < 4) ? r : (DD + r);
        sfp[row][ww_] = CLAMP;
        sfn[row][ww_] = CLAMP;
    }
    // Load + decode packed values (coalesced 128B per warp).
    #pragma unroll
    for (int r = tid; r < DD * WT3; r += 512) {
        int d = r >> 5, ww_ = r & 31;
        float x = g_x[base + d * HWSZ + ww_];
        sfp[4 + d][ww_] = fmaxf(x, 0.0f);
        sfn[4 + d][ww_] = fmaxf(-x, 0.0f);
    }
    __syncthreads();

    // Pull the 12 needed rows into registers (shared across 4 voxels).
    float rp[12], rn_[12];
    #pragma unroll
    for (int j = 0; j < 12; ++j) {
        rp[j]  = sfp[i0 + j][w];    // covers padded rows i0 .. i0+11
        rn_[j] = sfn[i0 + j][w];
    }

    float mArr[4], pcArr[4];
    #pragma unroll
    for (int j = 0; j < 4; ++j) {
        float bp = rp[j + 4];
        float bn = rn_[j + 4];
        #pragma unroll
        for (int k = 1; k <= 4; ++k) {
            float k2 = (float)(k * k);
            bp = fminf(bp, rp[j + 4 - k] + k2);
            bp = fminf(bp, rp[j + 4 + k] + k2);
            bn = fminf(bn, rn_[j + 4 - k] + k2);
            bn = fminf(bn, rn_[j + 4 + k] + k2);
        }
        mArr[j] = fmaxf(bp, bn);                    // exactly one is 0
        pcArr[j] = (bp > 0.0f) ? pv[j] : (1.0f - pv[j]);   // t==1 <=> bp>0
    }

    float accn, accd;
    bool fast = true;
    float prod = 1.0f;
    #pragma unroll
    for (int j = 0; j < 4; ++j) {
        if (mArr[j] > 9.0f) fast = false;
        prod *= pcArr[j];
    }
    if (fast && prod > 1e-30f) {
        accn = -__logf(prod);      // all w==1: sum(-log pc) == -log(prod)
        accd = 4.0f;
    } else {
        accn = 0.0f; accd = 0.0f;
        #pragma unroll
        for (int j = 0; j < 4; ++j) {
            float m = mArr[j];
            float wgt;
            if (m <= 9.0f)       wgt = 1.0f;
            else if (m >= 25.0f) wgt = 0.0f;
            else                 wgt = 1.0f - (sqrtf(m) - 3.0f) * 0.5f;
            float bce = -fmaxf(__logf(pcArr[j]), -100.0f);
            accn += bce * wgt;
            accd += wgt;
        }
    }

    #pragma unroll
    for (int off = 16; off > 0; off >>= 1) {
        accn += __shfl_down_sync(0xFFFFFFFFu, accn, off);
        accd += __shfl_down_sync(0xFFFFFFFFu, accd, off);
    }
    int warp = tid >> 5, lane = tid & 31;
    if (lane == 0) { rnm[warp] = accn; rdm[warp] = accd; }
    __syncthreads();
    if (tid == 0) {
        float sn = 0.0f, sd = 0.0f;
        #pragma unroll
        for (int j = 0; j < 16; ++j) { sn += rnm[j]; sd += rdm[j]; }
        g_pn[blockIdx.x] = sn;
        g_pd[blockIdx.x] = sd;
        __threadfence();
        unsigned old = atomicAdd(&g_count, 1u);
        s_last = (old == NBLK3 - 1) ? 1 : 0;
    }
    __syncthreads();

    // Last block: reduce all 576 partials -> scalar, reset counter.
    if (s_last) {
        __shared__ double wn[16], wd[16];
        const int PER_B = NBLK3 / BB;     // 288
        int rb = tid >> 8;                // 0..1 (batch)
        int j0 = tid & 255;
        double an = 0.0, ad = 0.0;
        #pragma unroll
        for (int j = j0; j < PER_B; j += 256) {
            an += (double)g_pn[rb * PER_B + j];
            ad += (double)g_pd[rb * PER_B + j];
        }
        #pragma unroll
        for (int off = 16; off > 0; off >>= 1) {
            an += __shfl_down_sync(0xFFFFFFFFu, an, off);
            ad += __shfl_down_sync(0xFFFFFFFFu, ad, off);
        }
        if (lane == 0) { wn[warp] = an; wd[warp] = ad; }
        __syncthreads();
        if (tid == 0) {
            double n0 = 0.0, dd0 = 0.0, n1 = 0.0, dd1 = 0.0;
            #pragma unroll
            for (int j = 0; j < 8; ++j)  { n0 += wn[j]; dd0 += wd[j]; }
            #pragma unroll
            for (int j = 8; j < 16; ++j) { n1 += wn[j]; dd1 += wd[j]; }
            double acc = n0 / (dd0 + 1e-5) + n1 / (dd1 + 1e-5);
            out[0] = (float)(acc / (double)BB);
            g_count = 0;   // reset for next graph replay
        }
    }
}

extern "C" void kernel_launch(void* const* d_in, const int* in_sizes, int n_in,
                              void* d_out, int out_size) {
    const float* pred = (const float*)d_in[0];
    const float* tgt  = (const float*)d_in[1];
    (void)in_sizes; (void)n_in; (void)out_size;

    k_passBC<<<NBLKBC, 256>>>(tgt);                 // 512 blocks
    k_pass3<<<NBLK3, 512>>>(pred, (float*)d_out);   // 576 blocks
}

// round 15
// speedup vs baseline: 1.1538x; 1.1538x over previous
#include <cuda_runtime.h>
#include <math.h>

#define BB 2
#define DD 64
#define HH 96
#define WW 96
#define VOL (DD*HH*WW)          // 589824
#define NVOX (BB*VOL)           // 1179648
#define HWSZ (HH*WW)            // 9216
#define NPLANE (BB*DD)          // 128
#define NROWS (NPLANE*HH)       // 12288
#define WT 32                   // passBC w-tile
#define HT 24                   // passBC h-tile (4 per plane)
#define WT3 16                  // pass3 w-tile
#define CLAMP 25.0f

#define NBLKBC (NPLANE*3*4)     // 1536 passBC blocks
#define NBLK3 (BB*HH*(WW/WT3))  // 1152 pass3 blocks

// Scratch (device globals: allocation-free per harness rules)
__device__ unsigned g_mask[NROWS][3];     // 96-bit row masks
__device__ float g_x[NVOX];               // packed bp-bn after W+H transform (clamped 25)
__device__ volatile float g_pn[NBLK3];
__device__ volatile float g_pd[NBLK3];
__device__ unsigned g_count;              // zero-init; last block resets -> deterministic

// Windowed nearest-set-bit distance: 96-bit local window {m0,m1,m2} covering
// [w0-32, w0+64); voxel at bit wl of m1. Clamp usage guarantees d<=5 matters.
__device__ __forceinline__ int win_dist(unsigned m0, unsigned m1, unsigned m2, int wl) {
    unsigned long long U = (unsigned long long)m1 | ((unsigned long long)m2 << 32);
    unsigned long long D = (unsigned long long)m0 | ((unsigned long long)m1 << 32);
    unsigned long long a = U >> wl;           // bit0 = self, upward
    unsigned long long b = D << (31 - wl);    // MSB = self, downward
    int up = a ? (__ffsll((long long)a) - 1) : 64;
    int dn = b ? __clzll((long long)b) : 64;
    return (up < dn) ? up : dn;
}

// Build row masks once: one warp per 4 rows -> 12 independent LDGs in flight
// (MLP=12) before the ballots, amortizing DRAM latency. Reads tgt exactly once.
__global__ __launch_bounds__(256) void k_mask(const float* __restrict__ tgt) {
    int gw = (blockIdx.x * 256 + threadIdx.x) >> 5;   // 0..NROWS/4-1
    int lane = threadIdx.x & 31;
    int row0 = gw * 4;
    const float* p = tgt + row0 * WW;
    float v[12];
    #pragma unroll
    for (int r = 0; r < 4; ++r) {
        v[3*r+0] = p[r * WW + lane];
        v[3*r+1] = p[r * WW + lane + 32];
        v[3*r+2] = p[r * WW + lane + 64];
    }
    #pragma unroll
    for (int r = 0; r < 4; ++r) {
        unsigned m0 = __ballot_sync(0xFFFFFFFFu, v[3*r+0] > 0.5f);
        unsigned m1 = __ballot_sync(0xFFFFFFFFu, v[3*r+1] > 0.5f);
        unsigned m2 = __ballot_sync(0xFFFFFFFFu, v[3*r+2] > 0.5f);
        if (lane == 0) {
            g_mask[row0 + r][0] = m0;
            g_mask[row0 + r][1] = m1;
            g_mask[row0 + r][2] = m2;
        }
    }
}

// Fused pass1 (clamped W bit-scan from masks) + pass2 (k=1..4 branch-free
// H stencil in smem). Block = (plane, h-tile 24, w-tile 32). Round-13 shape.
__global__ __launch_bounds__(256) void k_passBC() {
    __shared__ unsigned sm[32][3];      // rows h0-4..h0+27, segs wt-1..wt+1
    __shared__ float s1p[32][WT];
    __shared__ float s1n[32][WT];

    int blk = blockIdx.x;
    int wt = blk % 3;
    int ht = (blk / 3) & 3;
    int bd = blk / 12;
    int base = bd * HWSZ;
    int h0 = ht * HT;
    int tid = threadIdx.x;
    int lane = tid & 31;
    int warp = tid >> 5;                // 0..7

    // Load the 96 mask words (384 B) instead of re-ballots on tgt.
    if (tid < 96) {
        int r = tid / 3, s = tid - (tid / 3) * 3;
        int hr = h0 - 4 + r;
        int sw = wt - 1 + s;
        unsigned m = 0;
        if (hr >= 0 && hr < HH && sw >= 0 && sw < 3)
            m = g_mask[bd * HH + hr][sw];
        sm[r][s] = m;
    }
    __syncthreads();

    // pass1: clamped W-distance via windowed bit scan; out-of-plane rows -> CLAMP.
    unsigned val0 = (wt > 0) ? 0xFFFFFFFFu : 0u;
    unsigned val2 = (wt < 2) ? 0xFFFFFFFFu : 0u;
    #pragma unroll
    for (int r = warp; r < 32; r += 8) {
        int hr = h0 - 4 + r;
        float vp, vn;
        if (hr < 0 || hr >= HH) {
            vp = CLAMP; vn = CLAMP;
        } else {
            unsigned m0 = sm[r][0], m1 = sm[r][1], m2 = sm[r][2];
            int dn = win_dist(m0, m1, m2, lane);                       // nearest 1
            int dp = win_dist(val0 & ~m0, ~m1, val2 & ~m2, lane);      // nearest 0
            vp = (dp >= 5) ? CLAMP : (float)(dp * dp);
            vn = (dn >= 5) ? CLAMP : (float)(dn * dn);
        }
        s1p[r][lane] = vp;
        s1n[r][lane] = vn;
    }
    __syncthreads();

    // pass2 along H: fixed k=1..4 stencil (k=5 -> 25 >= clamp), rows 4..27.
    #pragma unroll
    for (int r4 = warp; r4 < HT; r4 += 8) {
        int r = r4 + 4;
        float bp = s1p[r][lane];
        float bn = s1n[r][lane];
        #pragma unroll
        for (int k = 1; k <= 4; ++k) {
            float k2 = (float)(k * k);
            bp = fminf(bp, s1p[r - k][lane] + k2);
            bp = fminf(bp, s1p[r + k][lane] + k2);
            bn = fminf(bn, s1n[r - k][lane] + k2);
            bn = fminf(bn, s1n[r + k][lane] + k2);
        }
        // Exactly one of bp,bn is 0 -> pack as signed value.
        g_x[base + (h0 + r4) * WW + wt * WT + lane] = bp - bn;
    }
}

// Pass3: k=1..4 D-stencil with 4-consecutive-i register reuse, fused loss
// epilogue (group-4 log) + grid-final reduction. Exact round-10/13 shape.
__global__ __launch_bounds__(256) void k_pass3(const float* __restrict__ pred,
                                               float* __restrict__ out) {
    __shared__ float sfp[DD + 8][17];   // stride 17: no bank conflicts
    __shared__ float sfn[DD + 8][17];
    __shared__ float rnm[8], rdm[8];
    __shared__ int s_last;

    int wt = blockIdx.x % (WW / WT3);       // 0..5
    int bh = blockIdx.x / (WW / WT3);
    int b = bh / HH;
    int h = bh % HH;
    int base = b * VOL + h * WW + wt * WT3;
    int tid = threadIdx.x;
    int w = tid & 15;
    int c0 = tid >> 4;                      // 0..15
    int i0 = c0 * 4;                        // 4 consecutive i per thread

    // Issue pred LDGs first (latency hidden behind smem fill + stencil).
    float pv[4];
    #pragma unroll
    for (int j = 0; j < 4; ++j) pv[j] = pred[base + (i0 + j) * HWSZ + w];

    // Pad rows [0..3] and [DD+4..DD+7].
    if (tid < 128) {
        int r = tid >> 4;
        int ww_ = tid & 15;
        int row = (r < 4) ? r : (DD + r);
        sfp[row][ww_] = CLAMP;
        sfn[row][ww_] = CLAMP;
    }
    // Load + decode packed values (coalesced 64B per 16 lanes).
    #pragma unroll
    for (int r = tid; r < DD * WT3; r += 256) {
        int d = r >> 4, ww_ = r & 15;
        float x = g_x[base + d * HWSZ + ww_];
        sfp[4 + d][ww_] = fmaxf(x, 0.0f);
        sfn[4 + d][ww_] = fmaxf(-x, 0.0f);
    }
    __syncthreads();

    // Pull the 12 needed rows into registers (shared across 4 voxels).
    float rp[12], rn_[12];
    #pragma unroll
    for (int j = 0; j < 12; ++j) {
        rp[j]  = sfp[i0 + j][w];    // covers padded rows i0 .. i0+11
        rn_[j] = sfn[i0 + j][w];
    }

    float mArr[4], pcArr[4];
    #pragma unroll
    for (int j = 0; j < 4; ++j) {
        float bp = rp[j + 4];
        float bn = rn_[j + 4];
        #pragma unroll
        for (int k = 1; k <= 4; ++k) {
            float k2 = (float)(k * k);
            bp = fminf(bp, rp[j + 4 - k] + k2);
            bp = fminf(bp, rp[j + 4 + k] + k2);
            bn = fminf(bn, rn_[j + 4 - k] + k2);
            bn = fminf(bn, rn_[j + 4 + k] + k2);
        }
        mArr[j] = fmaxf(bp, bn);                    // exactly one is 0
        pcArr[j] = (bp > 0.0f) ? pv[j] : (1.0f - pv[j]);   // t==1 <=> bp>0
    }

    float accn, accd;
    bool fast = true;
    float prod = 1.0f;
    #pragma unroll
    for (int j = 0; j < 4; ++j) {
        if (mArr[j] > 9.0f) fast = false;
        prod *= pcArr[j];
    }
    if (fast && prod > 1e-30f) {
        accn = -__logf(prod);      // all w==1: sum(-log pc) == -log(prod)
        accd = 4.0f;
    } else {
        accn = 0.0f; accd = 0.0f;
        #pragma unroll
        for (int j = 0; j < 4; ++j) {
            float m = mArr[j];
            float wgt;
            if (m <= 9.0f)       wgt = 1.0f;
            else if (m >= 25.0f) wgt = 0.0f;
            else                 wgt = 1.0f - (sqrtf(m) - 3.0f) * 0.5f;
            float bce = -fmaxf(__logf(pcArr[j]), -100.0f);
            accn += bce * wgt;
            accd += wgt;
        }
    }

    #pragma unroll
    for (int off = 16; off > 0; off >>= 1) {
        accn += __shfl_down_sync(0xFFFFFFFFu, accn, off);
        accd += __shfl_down_sync(0xFFFFFFFFu, accd, off);
    }
    int warp = tid >> 5, lane = tid & 31;
    if (lane == 0) { rnm[warp] = accn; rdm[warp] = accd; }
    __syncthreads();
    if (tid == 0) {
        float sn = 0.0f, sd = 0.0f;
        #pragma unroll
        for (int j = 0; j < 8; ++j) { sn += rnm[j]; sd += rdm[j]; }
        g_pn[blockIdx.x] = sn;
        g_pd[blockIdx.x] = sd;
        __threadfence();
        unsigned old = atomicAdd(&g_count, 1u);
        s_last = (old == NBLK3 - 1) ? 1 : 0;
    }
    __syncthreads();

    // Last block: reduce all 1152 partials -> scalar, reset counter.
    if (s_last) {
        __shared__ double wn[8], wd[8];
        const int PER_B = NBLK3 / BB;     // 576
        int rb = tid >> 7;                // 0..1 (batch)
        int j0 = tid & 127;
        double an = 0.0, ad = 0.0;
        #pragma unroll
        for (int j = j0; j < PER_B; j += 128) {
            an += (double)g_pn[rb * PER_B + j];
            ad += (double)g_pd[rb * PER_B + j];
        }
        #pragma unroll
        for (int off = 16; off > 0; off >>= 1) {
            an += __shfl_down_sync(0xFFFFFFFFu, an, off);
            ad += __shfl_down_sync(0xFFFFFFFFu, ad, off);
        }
        if (lane == 0) { wn[warp] = an; wd[warp] = ad; }
        __syncthreads();
        if (tid == 0) {
            double n0 = 0.0, dd0 = 0.0, n1 = 0.0, dd1 = 0.0;
            #pragma unroll
            for (int j = 0; j < 4; ++j) { n0 += wn[j]; dd0 += wd[j]; }
            #pragma unroll
            for (int j = 4; j < 8; ++j) { n1 += wn[j]; dd1 += wd[j]; }
            double acc = n0 / (dd0 + 1e-5) + n1 / (dd1 + 1e-5);
            out[0] = (float)(acc / (double)BB);
            g_count = 0;   // reset for next graph replay
        }
    }
}

extern "C" void kernel_launch(void* const* d_in, const int* in_sizes, int n_in,
                              void* d_out, int out_size) {
    const float* pred = (const float*)d_in[0];
    const float* tgt  = (const float*)d_in[1];
    (void)in_sizes; (void)n_in; (void)out_size;

    k_mask<<<NROWS / 4 / 8, 256>>>(tgt);            // 384 blocks, 4 rows/warp
    k_passBC<<<NBLKBC, 256>>>();                    // 1536 blocks
    k_pass3<<<NBLK3, 256>>>(pred, (float*)d_out);   // 1152 blocks
}

// round 16
// speedup vs baseline: 1.2824x; 1.1115x over previous
#include <cuda_runtime.h>
#include <math.h>

#define BB 2
#define DD 64
#define HH 96
#define WW 96
#define VOL (DD*HH*WW)          // 589824
#define NVOX (BB*VOL)           // 1179648
#define HWSZ (HH*WW)            // 9216
#define NPLANE (BB*DD)          // 128
#define HT 24                   // fused kernel h-tile (4 per plane)
#define WT3 16                  // pass3 w-tile
#define CLAMP 25.0f

#define NBLKBC (NPLANE*4)       // 512 fused blocks
#define NBLK3 (BB*HH*(WW/WT3))  // 1152 pass3 blocks

// Scratch (device globals: allocation-free per harness rules)
__device__ float g_x[NVOX];               // packed bp-bn after W+H transform (clamped 25)
__device__ volatile float g_pn[NBLK3];
__device__ volatile float g_pd[NBLK3];
__device__ unsigned g_count;              // zero-init; last block resets -> deterministic

// Windowed nearest-set-bit distance: 96-bit local window {m0,m1,m2} covering
// [seg*32-32, seg*32+64); voxel at bit wl of m1. Only d<=5 matters (clamp).
__device__ __forceinline__ int win_dist(unsigned m0, unsigned m1, unsigned m2, int wl) {
    unsigned long long U = (unsigned long long)m1 | ((unsigned long long)m2 << 32);
    unsigned long long D = (unsigned long long)m0 | ((unsigned long long)m1 << 32);
    unsigned long long a = U >> wl;           // bit0 = self, upward
    unsigned long long b = D << (31 - wl);    // MSB = self, downward
    int up = a ? (__ffsll((long long)a) - 1) : 64;
    int dn = b ? __clzll((long long)b) : 64;
    return (up < dn) ? up : dn;
}

// Fused: ballot mask build + pass1 (clamped W bit-scan, per-segment windows)
// + pass2 (k=1..4 branch-free H stencil). Block = (plane, full-W h-tile 24).
// tgt read redundancy only 1.33x (h-halo). 256 threads.
__global__ __launch_bounds__(256) void k_passBC(const float* __restrict__ tgt) {
    __shared__ unsigned sm[32][3];      // rows h0-4..h0+27, 3 segments each
    __shared__ float s1p[32 * WW];      // linear [row*96 + w]
    __shared__ float s1n[32 * WW];

    int ht = blockIdx.x & 3;
    int bd = blockIdx.x >> 2;
    int base = bd * HWSZ;
    int h0 = ht * HT;
    int tid = threadIdx.x;
    int lane = tid & 31;
    int warp = tid >> 5;                // 0..7

    // Ballot masks: 32 rows x 3 segs = 96 warp-tasks, 12 per warp.
    #pragma unroll
    for (int t = warp; t < 96; t += 8) {
        int r = t / 3;                  // const-div -> mul/shift
        int s = t - r * 3;
        int hr = h0 - 4 + r;
        float v = (hr >= 0 && hr < HH) ? tgt[base + hr * WW + s * 32 + lane] : 0.0f;
        unsigned m = __ballot_sync(0xFFFFFFFFu, v > 0.5f);
        if (lane == 0) sm[r][s] = m;
    }
    __syncthreads();

    // pass1: clamped W-distance via per-segment windowed bit scan.
    // 12 voxels/thread: 4 rows x 3 segments, voxel (r, s*32+lane).
    #pragma unroll
    for (int r = warp; r < 32; r += 8) {
        int hr = h0 - 4 + r;
        if (hr < 0 || hr >= HH) {
            #pragma unroll
            for (int s = 0; s < 3; ++s) {
                s1p[r * WW + s * 32 + lane] = CLAMP;
                s1n[r * WW + s * 32 + lane] = CLAMP;
            }
        } else {
            unsigned q0 = sm[r][0], q1 = sm[r][1], q2 = sm[r][2];
            #pragma unroll
            for (int s = 0; s < 3; ++s) {
                unsigned m0 = (s > 0) ? ((s == 1) ? q0 : q1) : 0u;
                unsigned m1 = (s == 0) ? q0 : ((s == 1) ? q1 : q2);
                unsigned m2 = (s < 2) ? ((s == 0) ? q1 : q2) : 0u;
                unsigned val0 = (s > 0) ? 0xFFFFFFFFu : 0u;
                unsigned val2 = (s < 2) ? 0xFFFFFFFFu : 0u;
                int dn = win_dist(m0, m1, m2, lane);                    // nearest 1
                int dp = win_dist(val0 & ~m0, ~m1, val2 & ~m2, lane);   // nearest 0
                s1p[r * WW + s * 32 + lane] = (dp >= 5) ? CLAMP : (float)(dp * dp);
                s1n[r * WW + s * 32 + lane] = (dn >= 5) ? CLAMP : (float)(dn * dn);
            }
        }
    }
    __syncthreads();

    // pass2 along H: fixed k=1..4 stencil (exact under clamp), 9 voxels/thread.
    #pragma unroll
    for (int v = tid; v < HT * WW; v += 256) {
        int i = v / WW;                 // const-div
        int c = v - i * WW;
        int rr = (i + 4) * WW + c;
        float bp = s1p[rr];
        float bn = s1n[rr];
        #pragma unroll
        for (int k = 1; k <= 4; ++k) {
            float k2 = (float)(k * k);
            bp = fminf(bp, s1p[rr - k * WW] + k2);
            bp = fminf(bp, s1p[rr + k * WW] + k2);
            bn = fminf(bn, s1n[rr - k * WW] + k2);
            bn = fminf(bn, s1n[rr + k * WW] + k2);
        }
        // Exactly one of bp,bn is 0 -> pack as signed value. Coalesced write.
        g_x[base + (h0 + i) * WW + c] = bp - bn;
    }
}

// Pass3: smem-free k=1..4 D-stencil (12 direct LDGs from L2-resident g_x),
// fused loss epilogue (group-4 log) + grid-final reduction.
__global__ __launch_bounds__(256) void k_pass3(const float* __restrict__ pred,
                                               float* __restrict__ out) {
    __shared__ float rnm[8], rdm[8];
    __shared__ int s_last;

    int wt = blockIdx.x % (WW / WT3);       // 0..5
    int bh = blockIdx.x / (WW / WT3);
    int b = bh / HH;
    int h = bh % HH;
    int base = b * VOL + h * WW + wt * WT3;
    int tid = threadIdx.x;
    int w = tid & 15;
    int c0 = tid >> 4;                      // 0..15
    int i0 = c0 * 4;                        // 4 consecutive i per thread

    // pred LDGs (DRAM) issued first; g_x LDGs (L2 hit) follow, all independent.
    float pv[4];
    #pragma unroll
    for (int j = 0; j < 4; ++j) pv[j] = pred[base + (i0 + j) * HWSZ + w];

    // 12-row window direct from global; out-of-range rows -> CLAMP (exact).
    float rp[12], rn_[12];
    #pragma unroll
    for (int j = 0; j < 12; ++j) {
        int d = i0 + j - 4;
        bool valid = ((unsigned)d < (unsigned)DD);
        float x = valid ? g_x[base + d * HWSZ + w] : 0.0f;
        rp[j]  = valid ? fmaxf(x, 0.0f)  : CLAMP;
        rn_[j] = valid ? fmaxf(-x, 0.0f) : CLAMP;
    }

    float mArr[4], pcArr[4];
    #pragma unroll
    for (int j = 0; j < 4; ++j) {
        float bp = rp[j + 4];
        float bn = rn_[j + 4];
        #pragma unroll
        for (int k = 1; k <= 4; ++k) {
            float k2 = (float)(k * k);
            bp = fminf(bp, rp[j + 4 - k] + k2);
            bp = fminf(bp, rp[j + 4 + k] + k2);
            bn = fminf(bn, rn_[j + 4 - k] + k2);
            bn = fminf(bn, rn_[j + 4 + k] + k2);
        }
        mArr[j] = fmaxf(bp, bn);                    // exactly one is 0
        pcArr[j] = (bp > 0.0f) ? pv[j] : (1.0f - pv[j]);   // t==1 <=> bp>0
    }

    float accn, accd;
    bool fast = true;
    float prod = 1.0f;
    #pragma unroll
    for (int j = 0; j < 4; ++j) {
        if (mArr[j] > 9.0f) fast = false;
        prod *= pcArr[j];
    }
    if (fast && prod > 1e-30f) {
        accn = -__logf(prod);      // all w==1: sum(-log pc) == -log(prod)
        accd = 4.0f;
    } else {
        accn = 0.0f; accd = 0.0f;
        #pragma unroll
        for (int j = 0; j < 4; ++j) {
            float m = mArr[j];
            float wgt;
            if (m <= 9.0f)       wgt = 1.0f;
            else if (m >= 25.0f) wgt = 0.0f;
            else                 wgt = 1.0f - (sqrtf(m) - 3.0f) * 0.5f;
            float bce = -fmaxf(__logf(pcArr[j]), -100.0f);
            accn += bce * wgt;
            accd += wgt;
        }
    }

    #pragma unroll
    for (int off = 16; off > 0; off >>= 1) {
        accn += __shfl_down_sync(0xFFFFFFFFu, accn, off);
        accd += __shfl_down_sync(0xFFFFFFFFu, accd, off);
    }
    int warp = tid >> 5, lane = tid & 31;
    if (lane == 0) { rnm[warp] = accn; rdm[warp] = accd; }
    __syncthreads();
    if (tid == 0) {
        float sn = 0.0f, sd = 0.0f;
        #pragma unroll
        for (int j = 0; j < 8; ++j) { sn += rnm[j]; sd += rdm[j]; }
        g_pn[blockIdx.x] = sn;
        g_pd[blockIdx.x] = sd;
        __threadfence();
        unsigned old = atomicAdd(&g_count, 1u);
        s_last = (old == NBLK3 - 1) ? 1 : 0;
    }
    __syncthreads();

    // Last block: reduce all 1152 partials -> scalar, reset counter.
    if (s_last) {
        __shared__ double wn[8], wd[8];
        const int PER_B = NBLK3 / BB;     // 576
        int rb = tid >> 7;                // 0..1 (batch)
        int j0 = tid & 127;
        double an = 0.0, ad = 0.0;
        #pragma unroll
        for (int j = j0; j < PER_B; j += 128) {
            an += (double)g_pn[rb * PER_B + j];
            ad += (double)g_pd[rb * PER_B + j];
        }
        #pragma unroll
        for (int off = 16; off > 0; off >>= 1) {
            an += __shfl_down_sync(0xFFFFFFFFu, an, off);
            ad += __shfl_down_sync(0xFFFFFFFFu, ad, off);
        }
        if (lane == 0) { wn[warp] = an; wd[warp] = ad; }
        __syncthreads();
        if (tid == 0) {
            double n0 = 0.0, dd0 = 0.0, n1 = 0.0, dd1 = 0.0;
            #pragma unroll
            for (int j = 0; j < 4; ++j) { n0 += wn[j]; dd0 += wd[j]; }
            #pragma unroll
            for (int j = 4; j < 8; ++j) { n1 += wn[j]; dd1 += wd[j]; }
            double acc = n0 / (dd0 + 1e-5) + n1 / (dd1 + 1e-5);
            out[0] = (float)(acc / (double)BB);
            g_count = 0;   // reset for next graph replay
        }
    }
}

extern "C" void kernel_launch(void* const* d_in, const int* in_sizes, int n_in,
                              void* d_out, int out_size) {
    const float* pred = (const float*)d_in[0];
    const float* tgt  = (const float*)d_in[1];
    (void)in_sizes; (void)n_in; (void)out_size;

    k_passBC<<<NBLKBC, 256>>>(tgt);                 // 512 blocks (mask fused)
    k_pass3<<<NBLK3, 256>>>(pred, (float*)d_out);   // 1152 blocks
}